// round 15
// baseline (speedup 1.0000x reference)
#include <cuda_runtime.h>
#include <cuda_fp16.h>
#include <math.h>
#include <stdint.h>

// Problem constants
#define BATCH 2
#define SEQ   2048
#define DMODEL 2048
#define NHEAD 16
#define HDIM  128
#define MROWS (BATCH*SEQ)          // 4096
#define WINDOW 512
#define QKV_ST (3*DMODEL)          // fused QKV row stride
// exp(s*SCALE - 3) via ex2: C1 = SCALE*log2e, C2 = -3*log2e
#define EXP_C1 0.12754334f
#define EXP_C2 (-4.32808512f)

// Scratch (device globals; no allocation allowed)
__device__ __align__(16) __half g_QKVh[ (size_t)MROWS * QKV_ST ];
__device__ __align__(16) __half g_AOh [ (size_t)MROWS * DMODEL ];
__device__ __align__(16) __half g_xh  [ (size_t)MROWS * DMODEL ];
__device__ __align__(16) __half g_Wh  [ (size_t)4 * DMODEL * DMODEL ];

// ---------------------------------------------------------------------------
// helpers
// ---------------------------------------------------------------------------
__device__ __forceinline__ uint32_t smem_u32(const void* p) {
    uint32_t a;
    asm("{ .reg .u64 t; cvta.to.shared.u64 t, %1; cvt.u32.u64 %0, t; }" : "=r"(a) : "l"(p));
    return a;
}

__device__ __forceinline__ void cp_async16(uint32_t dst, const void* src) {
    size_t g = __cvta_generic_to_global(src);
    asm volatile("cp.async.cg.shared.global [%0], [%1], 16;\n" :: "r"(dst), "l"(g));
}
#define CP_COMMIT() asm volatile("cp.async.commit_group;\n" ::: "memory")
#define CP_WAIT(n)  asm volatile("cp.async.wait_group %0;\n" :: "n"(n) : "memory")

__device__ __forceinline__ float ex2f(float x) {
    float r;
    asm("ex2.approx.ftz.f32 %0, %1;" : "=f"(r) : "f"(x));
    return r;
}

// fp16 mma m16n8k16, fp32 accumulate
__device__ __forceinline__ void mma16(float* c, const uint32_t* a, const uint32_t* b) {
    asm volatile(
        "mma.sync.aligned.m16n8k16.row.col.f32.f16.f16.f32 "
        "{%0,%1,%2,%3}, {%4,%5,%6,%7}, {%8,%9}, {%0,%1,%2,%3};"
        : "+f"(c[0]), "+f"(c[1]), "+f"(c[2]), "+f"(c[3])
        : "r"(a[0]), "r"(a[1]), "r"(a[2]), "r"(a[3]), "r"(b[0]), "r"(b[1]));
}

__device__ __forceinline__ uint32_t h2u(float x, float y) {
    __half2 h = __floats2half2_rn(x, y);
    return *(uint32_t*)&h;
}

__device__ __forceinline__ void ldm_x4(uint32_t* r, uint32_t addr) {
    asm volatile("ldmatrix.sync.aligned.m8n8.x4.shared.b16 {%0,%1,%2,%3}, [%4];"
        : "=r"(r[0]), "=r"(r[1]), "=r"(r[2]), "=r"(r[3]) : "r"(addr));
}
__device__ __forceinline__ void ldm_x4_trans(uint32_t* r, uint32_t addr) {
    asm volatile("ldmatrix.sync.aligned.m8n8.x4.trans.shared.b16 {%0,%1,%2,%3}, [%4];"
        : "=r"(r[0]), "=r"(r[1]), "=r"(r[2]), "=r"(r[3]) : "r"(addr));
}

__device__ __forceinline__ void store2(float* C, size_t idx, float a, float b) {
    *(float2*)&C[idx] = make_float2(a, b);
}
__device__ __forceinline__ void store2(__half* C, size_t idx, float a, float b) {
    *(__half2*)&C[idx] = __floats2half2_rn(a, b);
}

#define SWZ(o) ((o) ^ (((o) >> 3) & 0x70))

// ---------------------------------------------------------------------------
// Fused float -> half conversion (x + Wq + Wk + Wv + Wo in ONE launch)
// ---------------------------------------------------------------------------
#define N8X 1048576            // (MROWS*DMODEL)/8
#define N8W 524288             // (DMODEL*DMODEL)/8

__global__ __launch_bounds__(256)
void cvt_all_kernel(const float* __restrict__ x,
                    const float* __restrict__ w0, const float* __restrict__ w1,
                    const float* __restrict__ w2, const float* __restrict__ w3,
                    __half* __restrict__ xh, __half* __restrict__ wh) {
    int i = blockIdx.x * blockDim.x + threadIdx.x;
    const float4* src;
    uint4* dst;
    int idx;
    if (i < N8X) {
        src = (const float4*)x; dst = (uint4*)xh; idx = i;
    } else {
        int j = i - N8X;
        int sel = j >> 19;                 // j / N8W
        idx = j & (N8W - 1);
        src = (const float4*)((sel == 0) ? w0 : (sel == 1) ? w1 : (sel == 2) ? w2 : w3);
        dst = (uint4*)(wh + (size_t)sel * (8 * (size_t)N8W));
    }
    float4 v0 = src[2 * idx], v1 = src[2 * idx + 1];
    uint4 o;
    o.x = h2u(v0.x, v0.y); o.y = h2u(v0.z, v0.w);
    o.z = h2u(v1.x, v1.y); o.w = h2u(v1.z, v1.w);
    dst[idx] = o;
}

// ---------------------------------------------------------------------------
// fp16 GEMM (unchanged R14 champion): C = A * Bw^T, BKH=128 two-sub-block
// stages, NSTAGE=2, single-barrier pipeline. 192(QKV,DB) / 256(O-proj).
// ---------------------------------------------------------------------------
#define BM 128
#define BKH 128
#define A_BYTES (BM*128)

template <typename TO, int BN_, bool DB>
__global__ __launch_bounds__(256, 1)
void gemm_h(const __half* __restrict__ A, const __half* __restrict__ Bw,
            TO* __restrict__ C, int M, int N, int K) {
    constexpr int WN = BN_ / 4;
    constexpr int NT = WN / 8;
    constexpr int NB = WN / 16;
    constexpr int SUB = (BM + BN_) * 128;
    constexpr int STG = 2 * SUB;
    constexpr int BFILL = BN_ / 32;

    extern __shared__ char dsm[];
    const int tid  = threadIdx.x;
    const int lane = tid & 31;
    const int warp = tid >> 5;
    const int m0 = blockIdx.y * BM;
    const int n0 = blockIdx.x * BN_;
    const int NIT = K / BKH;

    const uint32_t sbase = (smem_u32(dsm) + 1023) & ~1023u;

    auto fill = [&](int it) {
        uint32_t stg = sbase + (it & 1) * STG;
#pragma unroll
        for (int sub = 0; sub < 2; sub++) {
            uint32_t st = stg + sub * SUB;
            size_t kb = (size_t)it * BKH + sub * 64;
#pragma unroll
            for (int i = 0; i < 4; i++) {
                int id = tid + i * 256;
                int row = id >> 3, c = id & 7;
                uint32_t off = (uint32_t)(row * 128 + c * 16);
                cp_async16(st + SWZ(off), A + (size_t)(m0 + row) * K + kb + c * 8);
            }
            uint32_t stB = st + A_BYTES;
#pragma unroll
            for (int i = 0; i < BFILL; i++) {
                int id = tid + i * 256;
                int row = id >> 3, c = id & 7;
                uint32_t off = (uint32_t)(row * 128 + c * 16);
                cp_async16(stB + SWZ(off), Bw + (size_t)(n0 + row) * K + kb + c * 8);
            }
        }
        CP_COMMIT();
    };

    float acc[4][NT][4];
#pragma unroll
    for (int mt = 0; mt < 4; mt++)
#pragma unroll
        for (int nt = 0; nt < NT; nt++)
#pragma unroll
            for (int r = 0; r < 4; r++) acc[mt][nt][r] = 0.f;

    fill(0);

    const int wm = (warp & 1) * 64;
    const int wn = (warp >> 1) * WN;
    const int a_row  = lane & 15;
    const int a_koff = (lane >> 4) * 8;
    const int b_row  = ((lane >> 4) << 3) + (lane & 7);
    const int b_koff = ((lane >> 3) & 1) * 8;

    auto load_a = [&](uint32_t (*a)[4], uint32_t stg, int kk) {
        uint32_t base = stg + (kk >> 6) * SUB;
        int kkl = kk & 63;
#pragma unroll
        for (int mt = 0; mt < 4; mt++) {
            uint32_t off = (uint32_t)((wm + mt * 16 + a_row) * 128 + (kkl + a_koff) * 2);
            ldm_x4(a[mt], base + SWZ(off));
        }
    };
    auto load_b = [&](uint32_t (*b)[2], uint32_t stg, int kk) {
        uint32_t base = stg + (kk >> 6) * SUB + A_BYTES;
        int kkl = kk & 63;
#pragma unroll
        for (int np = 0; np < NB; np++) {
            uint32_t off = (uint32_t)((wn + np * 16 + b_row) * 128 + (kkl + b_koff) * 2);
            uint32_t r4[4];
            ldm_x4(r4, base + SWZ(off));
            b[np * 2][0] = r4[0]; b[np * 2][1] = r4[1];
            b[np * 2 + 1][0] = r4[2]; b[np * 2 + 1][1] = r4[3];
        }
    };

    for (int j = 0; j < NIT; j++) {
        CP_WAIT(0);
        __syncthreads();
        if (j + 1 < NIT) fill(j + 1);

        uint32_t stg = sbase + (j & 1) * STG;
        if (DB) {
            uint32_t a[2][4][4], b[2][NT][2];
            load_a(a[0], stg, 0);
            load_b(b[0], stg, 0);
#pragma unroll
            for (int ki = 0; ki < BKH / 16; ki++) {
                const int cur = ki & 1, nxt = cur ^ 1;
                if (ki + 1 < BKH / 16) {
                    load_a(a[nxt], stg, (ki + 1) * 16);
                    load_b(b[nxt], stg, (ki + 1) * 16);
                }
#pragma unroll
                for (int mt = 0; mt < 4; mt++)
#pragma unroll
                    for (int nt = 0; nt < NT; nt++)
                        mma16(acc[mt][nt], a[cur][mt], b[cur][nt]);
            }
        } else {
#pragma unroll
            for (int kk = 0; kk < BKH; kk += 16) {
                uint32_t a[4][4], b[NT][2];
                load_a(a, stg, kk);
                load_b(b, stg, kk);
#pragma unroll
                for (int mt = 0; mt < 4; mt++)
#pragma unroll
                    for (int nt = 0; nt < NT; nt++)
                        mma16(acc[mt][nt], a[mt], b[nt]);
            }
        }
    }

#pragma unroll
    for (int mt = 0; mt < 4; mt++)
#pragma unroll
        for (int nt = 0; nt < NT; nt++) {
            int row = m0 + wm + mt * 16 + (lane >> 2);
            int col = n0 + wn + nt * 8 + (lane & 3) * 2;
            store2(C, (size_t)row * N + col,       acc[mt][nt][0], acc[mt][nt][1]);
            store2(C, (size_t)(row + 8) * N + col, acc[mt][nt][2], acc[mt][nt][3]);
        }
}

#define GEMM_SMEM_192 (2*2*(BM+192)*128 + 1024)
#define GEMM_SMEM_256 (2*2*(BM+256)*128 + 1024)

// ---------------------------------------------------------------------------
// Windowed flash attention — warp-pair decomposition.
// Q-tile 64 rows, 8 warps = 4 row-groups (16 rows) x 2 halves.
//   hf=0/1 splits: QK keys [hf*32,hf*32+32), PV head-dims [hf*64,hf*64+64).
// P halves exchanged via the dead K region of the current buffer (swizzled).
// Fixed-shift softmax; l combined across the pair once at the end.
// ---------------------------------------------------------------------------
#define QROWS 64
#define QST 136
#define KST 136
#define SMQ (QROWS * QST)            // 8704 halves
#define SMKV (64 * KST)              // 8704 halves per buffer
#define ATTN_SMEM_BYTES ((SMQ + 4 * SMKV) * 2)   // 87040 B

__global__ __launch_bounds__(256, 2)
void attn_h(const __half* __restrict__ QKV, __half* __restrict__ O) {
    extern __shared__ __half hsm[];
    __half* Qs = hsm;
    __half* Ks = hsm + SMQ;             // 2 bufs
    __half* Vs = hsm + SMQ + 2 * SMKV;  // 2 bufs

    const int tid  = threadIdx.x;
    const int lane = tid & 31;
    const int warp = tid >> 5;
    const int rg   = warp >> 1;        // row group 0..3
    const int hf   = warp & 1;         // half 0..1
    const int qt = blockIdx.x, head = blockIdx.y, b = blockIdx.z;
    const int q0 = qt * QROWS;

    const uint32_t sQ = smem_u32(Qs);
    const uint32_t sK = smem_u32(Ks);
    const uint32_t sV = smem_u32(Vs);

    const int jmin = (q0 > (WINDOW - 1)) ? (q0 - (WINDOW - 1)) : 0;
    const int t0 = jmin >> 6;
    const int t1 = (q0 + QROWS - 1) >> 6;

    auto fillKV = [&](int kt) {
        int buf = kt & 1;
        const __half* Kb = QKV + ((size_t)(b * SEQ + kt * 64)) * QKV_ST + DMODEL + head * HDIM;
        const __half* Vb = Kb + DMODEL;
#pragma unroll
        for (int i = 0; i < 4; i++) {
            int id = tid + i * 256;
            int row = id >> 4, c = id & 15;
            uint32_t doff = (uint32_t)(buf * SMKV + row * KST + c * 8) * 2;
            cp_async16(sK + doff, Kb + (size_t)row * QKV_ST + c * 8);
            cp_async16(sV + doff, Vb + (size_t)row * QKV_ST + c * 8);
        }
        CP_COMMIT();
    };

    {   // Q tile load (same cp.async group as fillKV(t0))
        const __half* Qb = QKV + ((size_t)(b * SEQ + q0)) * QKV_ST + head * HDIM;
#pragma unroll
        for (int i = 0; i < 4; i++) {
            int id = tid + i * 256;
            int row = id >> 4, c = id & 15;
            cp_async16(sQ + (uint32_t)(row * QST + c * 8) * 2,
                       Qb + (size_t)row * QKV_ST + c * 8);
        }
    }
    fillKV(t0);

    float o[8][4];
#pragma unroll
    for (int nt = 0; nt < 8; nt++)
#pragma unroll
        for (int r = 0; r < 4; r++) o[nt][r] = 0.f;
    float l0 = 0.f, l1 = 0.f;          // partial sums over own 32 keys

    const int i_min = q0 + rg * 16;
    const int i_max = i_min + 15;
    const int qrow  = i_min + (lane >> 2);
    const int a_row  = rg * 16 + (lane & 15);
    const int a_koff = (lane >> 4) * 8;
    const int b_row  = ((lane >> 4) << 3) + (lane & 7);
    const int b_koff = ((lane >> 3) & 1) * 8;

    for (int kt = t0; kt <= t1; kt++) {
        const int j0 = kt * 64;
        const int buf = kt & 1;
        CP_WAIT(0);
        __syncthreads();                       // (1) KV[buf] ready, prev PV done
        if (kt < t1) fillKV(kt + 1);

        bool aliveh[2];
        aliveh[0] = !((j0      > i_max) || (j0 + 31 + (WINDOW - 1) < i_min));
        aliveh[1] = !((j0 + 32 > i_max) || (j0 + 63 + (WINDOW - 1) < i_min));

        const uint32_t sKb = sK + (uint32_t)(buf * SMKV) * 2;
        const uint32_t sVb = sV + (uint32_t)(buf * SMKV) * 2;
        const uint32_t PB  = sKb;              // P stage reuses dead K region
        char* PBp = (char*)hsm + (size_t)(SMQ + buf * SMKV) * 2;

        float s[4][4];
        if (aliveh[hf]) {
#pragma unroll
            for (int nt = 0; nt < 4; nt++)
#pragma unroll
                for (int r = 0; r < 4; r++) s[nt][r] = 0.f;

#pragma unroll
            for (int kk = 0; kk < 128; kk += 16) {
                uint32_t a[4], bfr[4][2];
                ldm_x4(a, sQ + (uint32_t)(a_row * QST + kk + a_koff) * 2);
#pragma unroll
                for (int np = 0; np < 2; np++) {
                    uint32_t r4[4];
                    ldm_x4(r4, sKb + (uint32_t)((hf * 32 + np * 16 + b_row) * KST + kk + b_koff) * 2);
                    bfr[np * 2][0] = r4[0]; bfr[np * 2][1] = r4[1];
                    bfr[np * 2 + 1][0] = r4[2]; bfr[np * 2 + 1][1] = r4[3];
                }
#pragma unroll
                for (int nt = 0; nt < 4; nt++)
                    mma16(s[nt], a, bfr[nt]);
            }

            const bool need_mask = (j0 + hf * 32 + 31 > i_min) ||
                                   (j0 + hf * 32 < i_max - (WINDOW - 1));
            if (need_mask) {
#pragma unroll
                for (int nt = 0; nt < 4; nt++) {
#pragma unroll
                    for (int r = 0; r < 4; r++) {
                        int i = qrow + ((r >= 2) ? 8 : 0);
                        int j = j0 + hf * 32 + nt * 8 + (lane & 3) * 2 + (r & 1);
                        float p = ex2f(fmaf(s[nt][r], EXP_C1, EXP_C2));
                        if (j > i || j + (WINDOW - 1) < i) p = 0.f;
                        s[nt][r] = p;
                        if (r < 2) l0 += p; else l1 += p;
                    }
                }
            } else {
#pragma unroll
                for (int nt = 0; nt < 4; nt++) {
#pragma unroll
                    for (int r = 0; r < 4; r++) {
                        float p = ex2f(fmaf(s[nt][r], EXP_C1, EXP_C2));
                        s[nt][r] = p;
                        if (r < 2) l0 += p; else l1 += p;
                    }
                }
            }
        }

        __syncthreads();                       // (2) all K reads done -> K region free
        uint32_t pa[2][4];
        if (aliveh[hf]) {
            // pack own P A-fragments (chunks over own 32 keys)
#pragma unroll
            for (int c = 0; c < 2; c++) {
                pa[c][0] = h2u(s[2 * c][0],     s[2 * c][1]);
                pa[c][1] = h2u(s[2 * c][2],     s[2 * c][3]);
                pa[c][2] = h2u(s[2 * c + 1][0], s[2 * c + 1][1]);
                pa[c][3] = h2u(s[2 * c + 1][2], s[2 * c + 1][3]);
            }
            // STS own P block into stage (row-major 128B rows, swizzled)
#pragma unroll
            for (int nt = 0; nt < 4; nt++) {
                int key = hf * 32 + nt * 8 + (lane & 3) * 2;
                uint32_t off0 = (uint32_t)((rg * 16 + (lane >> 2)) * 128 + key * 2);
                *(uint32_t*)(PBp + SWZ(off0)) = pa[nt >> 1][(nt & 1) * 2 + 0] , // placeholder
                *(uint32_t*)(PBp + SWZ(off0)) = h2u(s[nt][0], s[nt][1]);
                uint32_t off1 = off0 + 8 * 128;
                *(uint32_t*)(PBp + SWZ(off1)) = h2u(s[nt][2], s[nt][3]);
            }
        }
        __syncthreads();                       // (3) P visible CTA-wide

        // PV: O[16 rows, hd hf*64..+64) += P[16, 64] * V[64, 64]
#pragma unroll
        for (int c = 0; c < 4; c++) {
            const int hh = c >> 1;
            if (!aliveh[hh]) continue;
            uint32_t af[4];
            if (hh == hf) {
                af[0] = pa[c & 1][0]; af[1] = pa[c & 1][1];
                af[2] = pa[c & 1][2]; af[3] = pa[c & 1][3];
            } else {
                uint32_t off = (uint32_t)((rg * 16 + (lane & 15)) * 128 + c * 32 + (lane >> 4) * 16);
                ldm_x4(af, PB + SWZ(off));
            }
#pragma unroll
            for (int ng = 0; ng < 4; ng++) {
                uint32_t v4[4];
                ldm_x4_trans(v4, sVb + (uint32_t)((c * 16 + (lane & 15)) * KST
                                                  + hf * 64 + ng * 16 + (lane >> 4) * 8) * 2);
                mma16(o[2 * ng],     af, v4);
                mma16(o[2 * ng + 1], af, v4 + 2);
            }
        }
    }

    // combine l across the warp pair via smem (Q region is dead now)
    __syncthreads();
    l0 += __shfl_xor_sync(0xffffffffu, l0, 1);
    l0 += __shfl_xor_sync(0xffffffffu, l0, 2);
    l1 += __shfl_xor_sync(0xffffffffu, l1, 1);
    l1 += __shfl_xor_sync(0xffffffffu, l1, 2);
    float* lst = (float*)Qs;     // 128 floats
    if ((lane & 3) == 0) {
        lst[hf * 64 + rg * 16 + (lane >> 2)]     = l0;
        lst[hf * 64 + rg * 16 + (lane >> 2) + 8] = l1;
    }
    __syncthreads();
    float L0 = lst[rg * 16 + (lane >> 2)]     + lst[64 + rg * 16 + (lane >> 2)];
    float L1 = lst[rg * 16 + (lane >> 2) + 8] + lst[64 + rg * 16 + (lane >> 2) + 8];
    float inv0 = 1.f / L0, inv1 = 1.f / L1;

    __half* Ob = O + ((size_t)(b * SEQ + q0 + rg * 16 + (lane >> 2))) * DMODEL
               + head * HDIM + hf * 64;
#pragma unroll
    for (int nt = 0; nt < 8; nt++) {
        int col = nt * 8 + (lane & 3) * 2;
        *(__half2*)&Ob[col] = __floats2half2_rn(o[nt][0] * inv0, o[nt][1] * inv0);
        *(__half2*)&Ob[(size_t)8 * DMODEL + col] = __floats2half2_rn(o[nt][2] * inv1, o[nt][3] * inv1);
    }
}

// ---------------------------------------------------------------------------
// Launch
// ---------------------------------------------------------------------------
extern "C" void kernel_launch(void* const* d_in, const int* in_sizes, int n_in,
                              void* d_out, int out_size) {
    const float* x  = (const float*)d_in[0];
    const float* Wq = (const float*)d_in[1];
    const float* Wk = (const float*)d_in[2];
    const float* Wv = (const float*)d_in[3];
    const float* Wo = (const float*)d_in[4];
    float* out = (float*)d_out;

    void *pQKV, *pAO, *pXH, *pWH;
    cudaGetSymbolAddress(&pQKV, g_QKVh);
    cudaGetSymbolAddress(&pAO,  g_AOh);
    cudaGetSymbolAddress(&pXH,  g_xh);
    cudaGetSymbolAddress(&pWH,  g_Wh);
    __half* xh = (__half*)pXH;
    __half* Wh = (__half*)pWH;
    const size_t DDn = (size_t)DMODEL * DMODEL;

    cudaFuncSetAttribute((gemm_h<__half, 192, true>),
                         cudaFuncAttributeMaxDynamicSharedMemorySize, GEMM_SMEM_192);
    cudaFuncSetAttribute((gemm_h<float, 256, false>),
                         cudaFuncAttributeMaxDynamicSharedMemorySize, GEMM_SMEM_256);
    cudaFuncSetAttribute(attn_h, cudaFuncAttributeMaxDynamicSharedMemorySize, ATTN_SMEM_BYTES);

    // one fused convert launch: x + Wq + Wk + Wv + Wo
    cvt_all_kernel<<<(N8X + 4 * N8W) / 256, 256>>>(x, Wq, Wk, Wv, Wo, xh, Wh);

    // Fused QKV projection, 128x192 tiles
    gemm_h<__half, 192, true><<<dim3(3 * DMODEL / 192, MROWS / BM), 256, GEMM_SMEM_192>>>(
        xh, Wh, (__half*)pQKV, MROWS, 3 * DMODEL, DMODEL);

    attn_h<<<dim3(SEQ / QROWS, NHEAD, BATCH), 256, ATTN_SMEM_BYTES>>>(
        (const __half*)pQKV, (__half*)pAO);

    gemm_h<float, 256, false><<<dim3(DMODEL / 256, MROWS / BM), 256, GEMM_SMEM_256>>>(
        (const __half*)pAO, Wh + 3 * DDn, out, MROWS, DMODEL, DMODEL);
}

// round 16
// speedup vs baseline: 1.5279x; 1.5279x over previous
#include <cuda_runtime.h>
#include <cuda_fp16.h>
#include <math.h>
#include <stdint.h>

// Problem constants
#define BATCH 2
#define SEQ   2048
#define DMODEL 2048
#define NHEAD 16
#define HDIM  128
#define MROWS (BATCH*SEQ)          // 4096
#define WINDOW 512
#define QKV_ST (3*DMODEL)          // fused QKV row stride
// exp(s*SCALE - 3) via ex2: C1 = SCALE*log2e, C2 = -3*log2e
#define EXP_C1 0.12754334f
#define EXP_C2 (-4.32808512f)

// Scratch (device globals; no allocation allowed)
__device__ __align__(16) __half g_QKVh[ (size_t)MROWS * QKV_ST ];
__device__ __align__(16) __half g_AOh [ (size_t)MROWS * DMODEL ];
__device__ __align__(16) __half g_xh  [ (size_t)MROWS * DMODEL ];
__device__ __align__(16) __half g_Wh  [ (size_t)4 * DMODEL * DMODEL ];

// ---------------------------------------------------------------------------
// helpers
// ---------------------------------------------------------------------------
__device__ __forceinline__ uint32_t smem_u32(const void* p) {
    uint32_t a;
    asm("{ .reg .u64 t; cvta.to.shared.u64 t, %1; cvt.u32.u64 %0, t; }" : "=r"(a) : "l"(p));
    return a;
}

__device__ __forceinline__ void cp_async16(uint32_t dst, const void* src) {
    size_t g = __cvta_generic_to_global(src);
    asm volatile("cp.async.cg.shared.global [%0], [%1], 16;\n" :: "r"(dst), "l"(g));
}
#define CP_COMMIT() asm volatile("cp.async.commit_group;\n" ::: "memory")
#define CP_WAIT(n)  asm volatile("cp.async.wait_group %0;\n" :: "n"(n) : "memory")

__device__ __forceinline__ float ex2f(float x) {
    float r;
    asm("ex2.approx.ftz.f32 %0, %1;" : "=f"(r) : "f"(x));
    return r;
}

// fp16 mma m16n8k16, fp32 accumulate
__device__ __forceinline__ void mma16(float* c, const uint32_t* a, const uint32_t* b) {
    asm volatile(
        "mma.sync.aligned.m16n8k16.row.col.f32.f16.f16.f32 "
        "{%0,%1,%2,%3}, {%4,%5,%6,%7}, {%8,%9}, {%0,%1,%2,%3};"
        : "+f"(c[0]), "+f"(c[1]), "+f"(c[2]), "+f"(c[3])
        : "r"(a[0]), "r"(a[1]), "r"(a[2]), "r"(a[3]), "r"(b[0]), "r"(b[1]));
}

__device__ __forceinline__ uint32_t h2u(float x, float y) {
    __half2 h = __floats2half2_rn(x, y);
    return *(uint32_t*)&h;
}

__device__ __forceinline__ void ldm_x4(uint32_t* r, uint32_t addr) {
    asm volatile("ldmatrix.sync.aligned.m8n8.x4.shared.b16 {%0,%1,%2,%3}, [%4];"
        : "=r"(r[0]), "=r"(r[1]), "=r"(r[2]), "=r"(r[3]) : "r"(addr));
}
__device__ __forceinline__ void ldm_x4_trans(uint32_t* r, uint32_t addr) {
    asm volatile("ldmatrix.sync.aligned.m8n8.x4.trans.shared.b16 {%0,%1,%2,%3}, [%4];"
        : "=r"(r[0]), "=r"(r[1]), "=r"(r[2]), "=r"(r[3]) : "r"(addr));
}

__device__ __forceinline__ void store2(float* C, size_t idx, float a, float b) {
    *(float2*)&C[idx] = make_float2(a, b);
}
__device__ __forceinline__ void store2(__half* C, size_t idx, float a, float b) {
    *(__half2*)&C[idx] = __floats2half2_rn(a, b);
}

#define SWZ(o) ((o) ^ (((o) >> 3) & 0x70))

// ---------------------------------------------------------------------------
// Fused float -> half conversion (x + Wq + Wk + Wv + Wo in ONE launch)
// ---------------------------------------------------------------------------
#define N8X 1048576            // (MROWS*DMODEL)/8
#define N8W 524288             // (DMODEL*DMODEL)/8

__global__ __launch_bounds__(256)
void cvt_all_kernel(const float* __restrict__ x,
                    const float* __restrict__ w0, const float* __restrict__ w1,
                    const float* __restrict__ w2, const float* __restrict__ w3,
                    __half* __restrict__ xh, __half* __restrict__ wh) {
    int i = blockIdx.x * blockDim.x + threadIdx.x;
    const float4* src;
    uint4* dst;
    int idx;
    if (i < N8X) {
        src = (const float4*)x; dst = (uint4*)xh; idx = i;
    } else {
        int j = i - N8X;
        int sel = j >> 19;                 // j / N8W
        idx = j & (N8W - 1);
        src = (const float4*)((sel == 0) ? w0 : (sel == 1) ? w1 : (sel == 2) ? w2 : w3);
        dst = (uint4*)(wh + (size_t)sel * (8 * (size_t)N8W));
    }
    float4 v0 = src[2 * idx], v1 = src[2 * idx + 1];
    uint4 o;
    o.x = h2u(v0.x, v0.y); o.y = h2u(v0.z, v0.w);
    o.z = h2u(v1.x, v1.y); o.w = h2u(v1.z, v1.w);
    dst[idx] = o;
}

// ---------------------------------------------------------------------------
// fp16 GEMM: C[M,N] = A[M,K](f16) * Bw[N,K](f16)^T, fp32 accum, OutT output.
// Unified template: BN_ tile width, DB fragment double-buffer, KCH 64-half
// sub-chunks per stage (stage K = KCH*64), NST pipeline stages.
//   QKV : <__half, 192, true,  2, 2>  (R14-proven)
//   Oproj: <float, 256, false, 1, 4>  (R11-proven)
// 8 warps 2x4, warp tile 64 x (BN_/4). 128B rows, SW128 xor swizzle.
// ---------------------------------------------------------------------------
#define BM 128
#define A_BYTES (BM*128)

template <typename TO, int BN_, bool DB, int KCH, int NST>
__global__ __launch_bounds__(256, 1)
void gemm_h(const __half* __restrict__ A, const __half* __restrict__ Bw,
            TO* __restrict__ C, int M, int N, int K) {
    constexpr int WN = BN_ / 4;
    constexpr int NT = WN / 8;
    constexpr int NB = WN / 16;
    constexpr int SUB = (BM + BN_) * 128;   // bytes per 64-half sub-chunk
    constexpr int STG = KCH * SUB;          // bytes per stage
    constexpr int BFILL = BN_ / 32;
    constexpr int KH = KCH * 64;            // halves of K per stage

    extern __shared__ char dsm[];
    const int tid  = threadIdx.x;
    const int lane = tid & 31;
    const int warp = tid >> 5;
    const int m0 = blockIdx.y * BM;
    const int n0 = blockIdx.x * BN_;
    const int NIT = K / KH;

    const uint32_t sbase = (smem_u32(dsm) + 1023) & ~1023u;

    auto fill = [&](int it) {
        uint32_t stg = sbase + (it % NST) * STG;
#pragma unroll
        for (int sub = 0; sub < KCH; sub++) {
            uint32_t st = stg + sub * SUB;
            size_t kb = (size_t)it * KH + sub * 64;
#pragma unroll
            for (int i = 0; i < 4; i++) {
                int id = tid + i * 256;
                int row = id >> 3, c = id & 7;
                uint32_t off = (uint32_t)(row * 128 + c * 16);
                cp_async16(st + SWZ(off), A + (size_t)(m0 + row) * K + kb + c * 8);
            }
            uint32_t stB = st + A_BYTES;
#pragma unroll
            for (int i = 0; i < BFILL; i++) {
                int id = tid + i * 256;
                int row = id >> 3, c = id & 7;
                uint32_t off = (uint32_t)(row * 128 + c * 16);
                cp_async16(stB + SWZ(off), Bw + (size_t)(n0 + row) * K + kb + c * 8);
            }
        }
        CP_COMMIT();
    };

    float acc[4][NT][4];
#pragma unroll
    for (int mt = 0; mt < 4; mt++)
#pragma unroll
        for (int nt = 0; nt < NT; nt++)
#pragma unroll
            for (int r = 0; r < 4; r++) acc[mt][nt][r] = 0.f;

#pragma unroll
    for (int p = 0; p < NST - 1; p++) fill(p);

    const int wm = (warp & 1) * 64;
    const int wn = (warp >> 1) * WN;
    const int a_row  = lane & 15;
    const int a_koff = (lane >> 4) * 8;
    const int b_row  = ((lane >> 4) << 3) + (lane & 7);
    const int b_koff = ((lane >> 3) & 1) * 8;

    auto load_a = [&](uint32_t (*a)[4], uint32_t stg, int kk) {
        uint32_t base = stg + (kk >> 6) * SUB;
        int kkl = kk & 63;
#pragma unroll
        for (int mt = 0; mt < 4; mt++) {
            uint32_t off = (uint32_t)((wm + mt * 16 + a_row) * 128 + (kkl + a_koff) * 2);
            ldm_x4(a[mt], base + SWZ(off));
        }
    };
    auto load_b = [&](uint32_t (*b)[2], uint32_t stg, int kk) {
        uint32_t base = stg + (kk >> 6) * SUB + A_BYTES;
        int kkl = kk & 63;
#pragma unroll
        for (int np = 0; np < NB; np++) {
            uint32_t off = (uint32_t)((wn + np * 16 + b_row) * 128 + (kkl + b_koff) * 2);
            uint32_t r4[4];
            ldm_x4(r4, base + SWZ(off));
            b[np * 2][0] = r4[0]; b[np * 2][1] = r4[1];
            b[np * 2 + 1][0] = r4[2]; b[np * 2 + 1][1] = r4[3];
        }
    };

    for (int j = 0; j < NIT; j++) {
        CP_WAIT(NST - 2);
        __syncthreads();
        if (j + NST - 1 < NIT) fill(j + NST - 1);

        uint32_t stg = sbase + (j % NST) * STG;
        if (DB) {
            uint32_t a[2][4][4], b[2][NT][2];
            load_a(a[0], stg, 0);
            load_b(b[0], stg, 0);
#pragma unroll
            for (int ki = 0; ki < KH / 16; ki++) {
                const int cur = ki & 1, nxt = cur ^ 1;
                if (ki + 1 < KH / 16) {
                    load_a(a[nxt], stg, (ki + 1) * 16);
                    load_b(b[nxt], stg, (ki + 1) * 16);
                }
#pragma unroll
                for (int mt = 0; mt < 4; mt++)
#pragma unroll
                    for (int nt = 0; nt < NT; nt++)
                        mma16(acc[mt][nt], a[cur][mt], b[cur][nt]);
            }
        } else {
#pragma unroll
            for (int kk = 0; kk < KH; kk += 16) {
                uint32_t a[4][4], b[NT][2];
                load_a(a, stg, kk);
                load_b(b, stg, kk);
#pragma unroll
                for (int mt = 0; mt < 4; mt++)
#pragma unroll
                    for (int nt = 0; nt < NT; nt++)
                        mma16(acc[mt][nt], a[mt], b[nt]);
            }
        }
    }

#pragma unroll
    for (int mt = 0; mt < 4; mt++)
#pragma unroll
        for (int nt = 0; nt < NT; nt++) {
            int row = m0 + wm + mt * 16 + (lane >> 2);
            int col = n0 + wn + nt * 8 + (lane & 3) * 2;
            store2(C, (size_t)row * N + col,       acc[mt][nt][0], acc[mt][nt][1]);
            store2(C, (size_t)(row + 8) * N + col, acc[mt][nt][2], acc[mt][nt][3]);
        }
}

#define GEMM_SMEM_QKV (2*2*(BM+192)*128 + 1024)   // NST=2, KCH=2, BN=192
#define GEMM_SMEM_OPR (4*1*(BM+256)*128 + 1024)   // NST=4, KCH=1, BN=256

// ---------------------------------------------------------------------------
// Windowed flash attention, fp16 mma + ldmatrix (exact R14 champion).
// ---------------------------------------------------------------------------
#define QST 136
#define KST 136
#define SMQ (128 * QST)
#define SMKV (64 * KST)
#define ATTN_SMEM_BYTES ((SMQ + 4 * SMKV) * 2)   // 104448 B

__global__ __launch_bounds__(256, 2)
void attn_h(const __half* __restrict__ QKV, __half* __restrict__ O) {
    extern __shared__ __half hsm[];
    __half* Qs = hsm;
    __half* Ks = hsm + SMQ;
    __half* Vs = hsm + SMQ + 2 * SMKV;

    const int tid  = threadIdx.x;
    const int lane = tid & 31;
    const int warp = tid >> 5;
    const int qt = blockIdx.x, h = blockIdx.y, b = blockIdx.z;
    const int q0 = qt * 128;

    const uint32_t sQ = smem_u32(Qs);
    const uint32_t sK = smem_u32(Ks);
    const uint32_t sV = smem_u32(Vs);

    const int jmin = (q0 > (WINDOW - 1)) ? (q0 - (WINDOW - 1)) : 0;
    const int t0 = jmin >> 6;
    const int t1 = (q0 + 127) >> 6;

    auto fillKV = [&](int kt) {
        int buf = kt & 1;
        const __half* Kb = QKV + ((size_t)(b * SEQ + kt * 64)) * QKV_ST + DMODEL + h * HDIM;
        const __half* Vb = Kb + DMODEL;
#pragma unroll
        for (int i = 0; i < 4; i++) {
            int id = tid + i * 256;
            int row = id >> 4, c = id & 15;
            uint32_t doff = (uint32_t)(buf * SMKV + row * KST + c * 8) * 2;
            cp_async16(sK + doff, Kb + (size_t)row * QKV_ST + c * 8);
            cp_async16(sV + doff, Vb + (size_t)row * QKV_ST + c * 8);
        }
        CP_COMMIT();
    };

    {
        const __half* Qb = QKV + ((size_t)(b * SEQ + q0)) * QKV_ST + h * HDIM;
#pragma unroll
        for (int i = 0; i < 8; i++) {
            int id = tid + i * 256;
            int row = id >> 4, c = id & 15;
            cp_async16(sQ + (uint32_t)(row * QST + c * 8) * 2,
                       Qb + (size_t)row * QKV_ST + c * 8);
        }
    }
    fillKV(t0);

    float o[16][4];
#pragma unroll
    for (int nt = 0; nt < 16; nt++)
#pragma unroll
        for (int r = 0; r < 4; r++) o[nt][r] = 0.f;
    float l0 = 0.f, l1 = 0.f;

    const int qrow  = q0 + warp * 16 + (lane >> 2);
    const int i_min = q0 + warp * 16;
    const int i_max = i_min + 15;
    const int a_row  = warp * 16 + (lane & 15);
    const int a_koff = (lane >> 4) * 8;
    const int b_row  = ((lane >> 4) << 3) + (lane & 7);
    const int b_koff = ((lane >> 3) & 1) * 8;
    const int v_krow = lane & 15;
    const int v_noff = (lane >> 4) * 8;

    for (int kt = t0; kt <= t1; kt++) {
        const int j0 = kt * 64;
        const int buf = kt & 1;
        CP_WAIT(0);
        __syncthreads();
        if (kt < t1) fillKV(kt + 1);

        const bool dead = (j0 > i_max) || (j0 + 63 + (WINDOW - 1) < i_min);
        if (dead) continue;
        const bool need_mask = (j0 + 63 > i_min) || (j0 < i_max - (WINDOW - 1));

        const uint32_t sKb = sK + (uint32_t)(buf * SMKV) * 2;
        const uint32_t sVb = sV + (uint32_t)(buf * SMKV) * 2;

        float s[8][4];
#pragma unroll
        for (int nt = 0; nt < 8; nt++)
#pragma unroll
            for (int r = 0; r < 4; r++) s[nt][r] = 0.f;

#pragma unroll
        for (int kk = 0; kk < 128; kk += 16) {
            uint32_t a[4], bfr[8][2];
            ldm_x4(a, sQ + (uint32_t)(a_row * QST + kk + a_koff) * 2);
#pragma unroll
            for (int np = 0; np < 4; np++) {
                uint32_t r4[4];
                ldm_x4(r4, sKb + (uint32_t)((np * 16 + b_row) * KST + kk + b_koff) * 2);
                bfr[np * 2][0] = r4[0]; bfr[np * 2][1] = r4[1];
                bfr[np * 2 + 1][0] = r4[2]; bfr[np * 2 + 1][1] = r4[3];
            }
#pragma unroll
            for (int nt = 0; nt < 8; nt++)
                mma16(s[nt], a, bfr[nt]);
        }

        if (need_mask) {
#pragma unroll
            for (int nt = 0; nt < 8; nt++) {
#pragma unroll
                for (int r = 0; r < 4; r++) {
                    int i = qrow + ((r >= 2) ? 8 : 0);
                    int j = j0 + nt * 8 + (lane & 3) * 2 + (r & 1);
                    float p = ex2f(fmaf(s[nt][r], EXP_C1, EXP_C2));
                    if (j > i || j + (WINDOW - 1) < i) p = 0.f;
                    s[nt][r] = p;
                    if (r < 2) l0 += p; else l1 += p;
                }
            }
        } else {
#pragma unroll
            for (int nt = 0; nt < 8; nt++) {
#pragma unroll
                for (int r = 0; r < 4; r++) {
                    float p = ex2f(fmaf(s[nt][r], EXP_C1, EXP_C2));
                    s[nt][r] = p;
                    if (r < 2) l0 += p; else l1 += p;
                }
            }
        }

        uint32_t pa[4][4];
#pragma unroll
        for (int ks = 0; ks < 4; ks++) {
            pa[ks][0] = h2u(s[2 * ks][0],     s[2 * ks][1]);
            pa[ks][1] = h2u(s[2 * ks][2],     s[2 * ks][3]);
            pa[ks][2] = h2u(s[2 * ks + 1][0], s[2 * ks + 1][1]);
            pa[ks][3] = h2u(s[2 * ks + 1][2], s[2 * ks + 1][3]);
        }

#pragma unroll
        for (int ks = 0; ks < 4; ks++) {
#pragma unroll
            for (int ng = 0; ng < 8; ng++) {
                uint32_t r4[4];
                ldm_x4_trans(r4, sVb + (uint32_t)((ks * 16 + v_krow) * KST + ng * 16 + v_noff) * 2);
                mma16(o[2 * ng],     pa[ks], r4);
                mma16(o[2 * ng + 1], pa[ks], r4 + 2);
            }
        }
    }

    l0 += __shfl_xor_sync(0xffffffffu, l0, 1);
    l0 += __shfl_xor_sync(0xffffffffu, l0, 2);
    l1 += __shfl_xor_sync(0xffffffffu, l1, 1);
    l1 += __shfl_xor_sync(0xffffffffu, l1, 2);
    float inv0 = 1.f / l0, inv1 = 1.f / l1;

    __half* Ob = O + ((size_t)(b * SEQ + q0 + warp * 16 + (lane >> 2))) * DMODEL + h * HDIM;
#pragma unroll
    for (int nt = 0; nt < 16; nt++) {
        int col = nt * 8 + (lane & 3) * 2;
        *(__half2*)&Ob[col] = __floats2half2_rn(o[nt][0] * inv0, o[nt][1] * inv0);
        *(__half2*)&Ob[(size_t)8 * DMODEL + col] = __floats2half2_rn(o[nt][2] * inv1, o[nt][3] * inv1);
    }
}

// ---------------------------------------------------------------------------
// Launch
// ---------------------------------------------------------------------------
extern "C" void kernel_launch(void* const* d_in, const int* in_sizes, int n_in,
                              void* d_out, int out_size) {
    const float* x  = (const float*)d_in[0];
    const float* Wq = (const float*)d_in[1];
    const float* Wk = (const float*)d_in[2];
    const float* Wv = (const float*)d_in[3];
    const float* Wo = (const float*)d_in[4];
    float* out = (float*)d_out;

    void *pQKV, *pAO, *pXH, *pWH;
    cudaGetSymbolAddress(&pQKV, g_QKVh);
    cudaGetSymbolAddress(&pAO,  g_AOh);
    cudaGetSymbolAddress(&pXH,  g_xh);
    cudaGetSymbolAddress(&pWH,  g_Wh);
    __half* xh = (__half*)pXH;
    __half* Wh = (__half*)pWH;
    const size_t DDn = (size_t)DMODEL * DMODEL;

    cudaFuncSetAttribute((gemm_h<__half, 192, true, 2, 2>),
                         cudaFuncAttributeMaxDynamicSharedMemorySize, GEMM_SMEM_QKV);
    cudaFuncSetAttribute((gemm_h<float, 256, false, 1, 4>),
                         cudaFuncAttributeMaxDynamicSharedMemorySize, GEMM_SMEM_OPR);
    cudaFuncSetAttribute(attn_h, cudaFuncAttributeMaxDynamicSharedMemorySize, ATTN_SMEM_BYTES);

    // one fused convert launch: x + Wq + Wk + Wv + Wo
    cvt_all_kernel<<<(N8X + 4 * N8W) / 256, 256>>>(x, Wq, Wk, Wv, Wo, xh, Wh);

    // Fused QKV projection, 128x192 tiles, BKH=128/NST=2 (R14-proven)
    gemm_h<__half, 192, true, 2, 2><<<dim3(3 * DMODEL / 192, MROWS / BM), 256, GEMM_SMEM_QKV>>>(
        xh, Wh, (__half*)pQKV, MROWS, 3 * DMODEL, DMODEL);

    attn_h<<<dim3(SEQ / 128, NHEAD, BATCH), 256, ATTN_SMEM_BYTES>>>(
        (const __half*)pQKV, (__half*)pAO);

    // O-projection, 128x256 tiles, BKH=64/NST=4 (R11-proven)
    gemm_h<float, 256, false, 1, 4><<<dim3(DMODEL / 256, MROWS / BM), 256, GEMM_SMEM_OPR>>>(
        (const __half*)pAO, Wh + 3 * DDn, out, MROWS, DMODEL, DMODEL);
}